// round 6
// baseline (speedup 1.0000x reference)
#include <cuda_runtime.h>
#include <cuda_fp16.h>

#define L_FRAMES 16
#define C_CH     16
#define H_DIM    128
#define W_DIM    256
#define HW       (H_DIM * W_DIM)
#define DECAY_F  0.1f

// Two parity copies of channel-last fp16 scratch, 16 MB each (32 MB total).
// copy0: [k][h][w][c] (slot w = pixel w)
// copy1: rotated by one pixel in x (slot s = pixel (s+1) & 255)
// For tap pair (x0, x0+1), copy (x0&1) holds the 64B group aligned at slot x0&~1.
#define COPY_BYTES (L_FRAMES * HW * C_CH * 2)   // 16 MB = 1<<24
__device__ __half  g_imgT[2 * L_FRAMES * HW * C_CH];
// Interleaved flow: [k][h][w] float2, 4 MB
__device__ float2 g_flow2[L_FRAMES * HW];

// ---------------------------------------------------------------------------
// Prep: transpose img [k][c][h][w] fp32 -> fp16 channel-last, write both
// parity copies; pack flow to float2.
// ---------------------------------------------------------------------------
__global__ void prep_kernel(const float* __restrict__ img,
                            const float* __restrict__ cum_flow) {
    const int kh = blockIdx.x;          // k*H + h
    const int w  = threadIdx.x;         // 0..255
    const int k  = kh >> 7;
    const int h  = kh & (H_DIM - 1);

    __half2 v[8];
#pragma unroll
    for (int c = 0; c < 8; c++) {
        float a = img[((k * C_CH + 2 * c + 0) * H_DIM + h) * W_DIM + w];
        float b = img[((k * C_CH + 2 * c + 1) * H_DIM + h) * W_DIM + w];
        v[c] = __floats2half2_rn(a, b);
    }

    const unsigned row = (unsigned)kh * W_DIM;          // slot row base
    char* g = reinterpret_cast<char*>(g_imgT);

    // copy0: slot w
    uint4* d0 = reinterpret_cast<uint4*>(g + ((size_t)(row + w) << 5));
    d0[0] = *reinterpret_cast<const uint4*>(&v[0]);
    d0[1] = *reinterpret_cast<const uint4*>(&v[4]);
    // copy1: slot (w-1) & 255
    const unsigned s1 = row + ((w - 1) & (W_DIM - 1));
    uint4* d1 = reinterpret_cast<uint4*>(g + COPY_BYTES + ((size_t)s1 << 5));
    d1[0] = *reinterpret_cast<const uint4*>(&v[0]);
    d1[1] = *reinterpret_cast<const uint4*>(&v[4]);

    const int p = h * W_DIM + w;
    const float fx = cum_flow[(k * 2 + 0) * HW + p];
    const float fy = cum_flow[(k * 2 + 1) * HW + p];
    g_flow2[k * HW + p] = make_float2(fx, fy);
}

// ---------------------------------------------------------------------------
// Warped accumulation. blockIdx.y = t, blockIdx.x covers 64 pixels.
// 4 lanes per pixel: ch = sub&1 (16B channel half), xh = sub>>1 (x tap).
// Parity-copy selection makes every pixel's 64B tap group line-aligned:
// one L1 line per pixel per img LDG.
// ---------------------------------------------------------------------------
__global__ void __launch_bounds__(256) sample_kernel(
    const float* __restrict__ mask,       // [t][k]
    const float* __restrict__ dist,       // [t][k]
    float* __restrict__ out)              // [t][c][h][w]
{
    const int t = blockIdx.y;

    __shared__ float ws[L_FRAMES];
    if (threadIdx.x < L_FRAMES) {
        int i = t * L_FRAMES + threadIdx.x;
        ws[threadIdx.x] = mask[i] * expf(-DECAY_F * dist[i]);
    }
    __syncthreads();

    const int tid = threadIdx.x;
    const int sub = tid & 3;
    const int ch  = sub & 1;        // channel half: channels [ch*8, ch*8+8)
    const int xh  = sub >> 1;       // x tap: 0 -> x0, 1 -> x0+1
    const int p   = blockIdx.x * 64 + (tid >> 2);   // pixel 0..32767
    const int h   = p >> 8;
    const int w   = p & (W_DIM - 1);

    const float2 ft = g_flow2[t * HW + p];

    // Hoisted affine coords: ix = Ax - 128*fkx ; iy = Ay - 64*fky
    const float base_x = (float)w * (2.0f / W_DIM) - 1.0f + (1.0f / W_DIM);
    const float base_y = (float)h * (2.0f / H_DIM) - 1.0f + (1.0f / H_DIM);
    const float Ax = (base_x + ft.x + 1.0f) * (W_DIM * 0.5f) - 0.5f;
    const float Ay = (base_y + ft.y + 1.0f) * (H_DIM * 0.5f) - 0.5f;

    // xw = xh ? wx : 1-wx  ->  xw = fma(sx, wx, cx)
    const float sx = xh ? 1.0f : -1.0f;
    const float cx = xh ? 0.0f : 1.0f;

    float acc[8];
#pragma unroll
    for (int j = 0; j < 8; j++) acc[j] = 0.0f;

    // per-lane byte base: channel-half (16B) + x-tap (32B); k adds HW*32.
    const char* __restrict__ kbase =
        reinterpret_cast<const char*>(g_imgT) + ch * 16 + xh * 32;
    const float2* __restrict__ flow = g_flow2 + p;

    for (int k = 0; k <= t; k++) {
        const float wk  = ws[k];
        const float2 fk = *flow;
        flow += HW;

        const float ix = fmaf(-(W_DIM * 0.5f), fk.x, Ax);
        const float iy = fmaf(-(H_DIM * 0.5f), fk.y, Ay);

        const int x0 = __float2int_rd(ix);
        const int y0 = __float2int_rd(iy);
        const float wx = ix - (float)x0;
        const float wy = iy - (float)y0;

        const int x0w = x0 & (W_DIM - 1);
        const int y0c = min(max(y0, 0), H_DIM - 1);
        const int y1c = min(max(y0 + 1, 0), H_DIM - 1);

        const float xw = fmaf(sx, wx, cx);
        const float tw = wk * xw;
        const float w1 = tw * wy;
        const float w0 = tw - w1;

        const __half2 w0h = __float2half2_rn(w0);
        const __half2 w1h = __float2half2_rn(w1);

        // parity copy select + aligned slot: whole 64B tap group is one line
        const unsigned xoff = ((unsigned)(x0w & 1) << 24)         // copy select
                            + ((unsigned)(x0w & ~1) << 5);        // aligned slot
        const unsigned off0 = ((unsigned)y0c << 13) + xoff;
        const unsigned off1 = ((unsigned)y1c << 13) + xoff;

        const uint4 u0 = *reinterpret_cast<const uint4*>(kbase + off0);
        const uint4 u1 = *reinterpret_cast<const uint4*>(kbase + off1);
        kbase += HW * 32;

        const __half2* h0 = reinterpret_cast<const __half2*>(&u0);
        const __half2* h1 = reinterpret_cast<const __half2*>(&u1);
#pragma unroll
        for (int j = 0; j < 4; j++) {
            __half2 s = __hmul2(h0[j], w0h);
            s = __hfma2(h1[j], w1h, s);
            const float2 f = __half22float2(s);
            acc[2 * j + 0] += f.x;
            acc[2 * j + 1] += f.y;
        }
    }

    // merge x-halves: partner lane differs in bit 1 of tid
#pragma unroll
    for (int j = 0; j < 8; j++)
        acc[j] += __shfl_xor_sync(0xffffffffu, acc[j], 2);

    // each lane writes 4 channels: [ch*8 + xh*4, +4)
    const int cbase = (t * C_CH + ch * 8 + xh * 4) * HW + p;
#pragma unroll
    for (int j = 0; j < 4; j++)
        out[cbase + j * HW] = acc[xh * 4 + j];
}

extern "C" void kernel_launch(void* const* d_in, const int* in_sizes, int n_in,
                              void* d_out, int out_size) {
    const float* img      = (const float*)d_in[0];  // (1,16,16,128,256)
    const float* cum_flow = (const float*)d_in[1];  // (1,16,2,128,256)
    const float* mask     = (const float*)d_in[2];  // (16,16)
    const float* dist     = (const float*)d_in[3];  // (16,16)
    float* out            = (float*)d_out;          // (1,16,16,128,256)

    prep_kernel<<<L_FRAMES * H_DIM, W_DIM>>>(img, cum_flow);

    dim3 grid(HW / 64, L_FRAMES);   // 512 x 16 blocks
    sample_kernel<<<grid, 256>>>(mask, dist, out);
}

// round 7
// speedup vs baseline: 1.0526x; 1.0526x over previous
#include <cuda_runtime.h>
#include <cuda_fp16.h>

#define L_FRAMES 16
#define C_CH     16
#define H_DIM    128
#define W_DIM    256
#define HW       (H_DIM * W_DIM)
#define DECAY_F  0.1f

// Channel-last fp16 scratch: [k][h][w][c], 16 MB
__device__ __half  g_imgT[L_FRAMES * HW * C_CH];
// Interleaved flow: [k][h][w] float2, 4 MB
__device__ float2 g_flow2[L_FRAMES * HW];

// ---------------------------------------------------------------------------
// Prep: transpose img [k][c][h][w] fp32 -> [k][h][w][c] fp16, pack flow.
// ---------------------------------------------------------------------------
__global__ void prep_kernel(const float* __restrict__ img,
                            const float* __restrict__ cum_flow) {
    const int kh = blockIdx.x;          // k*H + h
    const int w  = threadIdx.x;         // 0..255
    const int k  = kh >> 7;
    const int h  = kh & (H_DIM - 1);

    __half2 v[8];
#pragma unroll
    for (int c = 0; c < 8; c++) {
        float a = img[((k * C_CH + 2 * c + 0) * H_DIM + h) * W_DIM + w];
        float b = img[((k * C_CH + 2 * c + 1) * H_DIM + h) * W_DIM + w];
        v[c] = __floats2half2_rn(a, b);
    }
    uint4* dst = reinterpret_cast<uint4*>(&g_imgT[((size_t)kh * W_DIM + w) * C_CH]);
    dst[0] = *reinterpret_cast<const uint4*>(&v[0]);
    dst[1] = *reinterpret_cast<const uint4*>(&v[4]);

    const int p = h * W_DIM + w;
    const float fx = cum_flow[(k * 2 + 0) * HW + p];
    const float fy = cum_flow[(k * 2 + 1) * HW + p];
    g_flow2[k * HW + p] = make_float2(fx, fy);
}

// ---------------------------------------------------------------------------
// Warped accumulation. blockIdx.y = t, blockIdx.x covers 64 pixels.
// 4 lanes per pixel: ch = sub&1 (16B channel half), xh = sub>>1 (x tap).
// All 16 k-flows for the block's 64 pixels staged in SMEM once, so the
// k-loop's dependent chain is LDS(29cyc) -> coords -> img LDG. k unrolled x2.
// ---------------------------------------------------------------------------
__global__ void __launch_bounds__(256) sample_kernel(
    const float* __restrict__ mask,       // [t][k]
    const float* __restrict__ dist,       // [t][k]
    float* __restrict__ out)              // [t][c][h][w]
{
    const int t = blockIdx.y;
    const int p0 = blockIdx.x * 64;

    __shared__ float  ws[L_FRAMES];
    __shared__ float2 sflow[L_FRAMES * 64];   // [k][px], 8 KB

    if (threadIdx.x < L_FRAMES) {
        int i = t * L_FRAMES + threadIdx.x;
        ws[threadIdx.x] = mask[i] * expf(-DECAY_F * dist[i]);
    }
    // cooperative flow stage: 1024 float2, 256 threads -> 4 each, coalesced
#pragma unroll
    for (int i = 0; i < 4; i++) {
        const int idx = threadIdx.x + i * 256;      // k*64 + px
        const int kk  = idx >> 6;
        const int px  = idx & 63;
        sflow[idx] = g_flow2[kk * HW + p0 + px];
    }
    __syncthreads();

    const int tid = threadIdx.x;
    const int sub = tid & 3;
    const int ch  = sub & 1;        // channel half: channels [ch*8, ch*8+8)
    const int xh  = sub >> 1;       // x tap: 0 -> x0, 1 -> x0+1
    const int px  = tid >> 2;       // pixel-in-block 0..63
    const int p   = p0 + px;
    const int h   = p >> 8;
    const int w   = p & (W_DIM - 1);

    const float2 ft = sflow[t * 64 + px];

    // Hoisted affine coords: ix = Ax - 128*fkx ; iy = Ay - 64*fky
    const float base_x = (float)w * (2.0f / W_DIM) - 1.0f + (1.0f / W_DIM);
    const float base_y = (float)h * (2.0f / H_DIM) - 1.0f + (1.0f / H_DIM);
    const float Ax = (base_x + ft.x + 1.0f) * (W_DIM * 0.5f) - 0.5f;
    const float Ay = (base_y + ft.y + 1.0f) * (H_DIM * 0.5f) - 0.5f;

    // xw = xh ? wx : 1-wx  ->  xw = fma(sx, wx, cx)
    const float sx = xh ? 1.0f : -1.0f;
    const float cx = xh ? 0.0f : 1.0f;

    float acc[8];
#pragma unroll
    for (int j = 0; j < 8; j++) acc[j] = 0.0f;

    // per-lane byte base: channel-half (16B); k advances by HW*32 bytes
    const char* __restrict__ gbase =
        reinterpret_cast<const char*>(g_imgT) + ch * 16;

#define BODY(kk)                                                               \
    {                                                                          \
        const int _k = (kk);                                                   \
        const float wk  = ws[_k];                                              \
        const float2 fk = sflow[_k * 64 + px];                                 \
        const float ix = fmaf(-(W_DIM * 0.5f), fk.x, Ax);                      \
        const float iy = fmaf(-(H_DIM * 0.5f), fk.y, Ay);                      \
        const int x0 = __float2int_rd(ix);                                     \
        const int y0 = __float2int_rd(iy);                                     \
        const float wx = ix - (float)x0;                                       \
        const float wy = iy - (float)y0;                                       \
        const int x   = (x0 + xh) & (W_DIM - 1);                               \
        const int y0c = min(max(y0, 0), H_DIM - 1);                            \
        const int y1c = min(max(y0 + 1, 0), H_DIM - 1);                        \
        const float xw = fmaf(sx, wx, cx);                                     \
        const float tw = wk * xw;                                              \
        const float w1 = tw * wy;                                              \
        const float w0 = tw - w1;                                              \
        const __half2 w0h = __float2half2_rn(w0);                              \
        const __half2 w1h = __float2half2_rn(w1);                              \
        const unsigned kb   = (unsigned)(_k * HW) << 5;                        \
        const unsigned ox   = (unsigned)x << 5;                                \
        const unsigned off0 = kb + ((unsigned)y0c << 13) + ox;                 \
        const unsigned off1 = kb + ((unsigned)y1c << 13) + ox;                 \
        const uint4 u0 = *reinterpret_cast<const uint4*>(gbase + off0);        \
        const uint4 u1 = *reinterpret_cast<const uint4*>(gbase + off1);        \
        const __half2* h0 = reinterpret_cast<const __half2*>(&u0);             \
        const __half2* h1 = reinterpret_cast<const __half2*>(&u1);             \
        _Pragma("unroll")                                                      \
        for (int j = 0; j < 4; j++) {                                          \
            __half2 s = __hmul2(h0[j], w0h);                                   \
            s = __hfma2(h1[j], w1h, s);                                        \
            const float2 f = __half22float2(s);                                \
            acc[2 * j + 0] += f.x;                                             \
            acc[2 * j + 1] += f.y;                                             \
        }                                                                      \
    }

    int k = 0;
    for (; k + 1 <= t; k += 2) {
        BODY(k);
        BODY(k + 1);
    }
    if (k <= t) BODY(k);
#undef BODY

    // merge x-halves: partner lane differs in bit 1 of tid
#pragma unroll
    for (int j = 0; j < 8; j++)
        acc[j] += __shfl_xor_sync(0xffffffffu, acc[j], 2);

    // each lane writes 4 channels: [ch*8 + xh*4, +4)
    const int cbase = (t * C_CH + ch * 8 + xh * 4) * HW + p;
#pragma unroll
    for (int j = 0; j < 4; j++)
        out[cbase + j * HW] = acc[xh * 4 + j];
}

extern "C" void kernel_launch(void* const* d_in, const int* in_sizes, int n_in,
                              void* d_out, int out_size) {
    const float* img      = (const float*)d_in[0];  // (1,16,16,128,256)
    const float* cum_flow = (const float*)d_in[1];  // (1,16,2,128,256)
    const float* mask     = (const float*)d_in[2];  // (16,16)
    const float* dist     = (const float*)d_in[3];  // (16,16)
    float* out            = (float*)d_out;          // (1,16,16,128,256)

    prep_kernel<<<L_FRAMES * H_DIM, W_DIM>>>(img, cum_flow);

    dim3 grid(HW / 64, L_FRAMES);   // 512 x 16 blocks
    sample_kernel<<<grid, 256>>>(mask, dist, out);
}

// round 8
// speedup vs baseline: 1.0857x; 1.0315x over previous
#include <cuda_runtime.h>
#include <cuda_fp16.h>

#define L_FRAMES 16
#define C_CH     16
#define H_DIM    128
#define W_DIM    256
#define HW       (H_DIM * W_DIM)
#define DECAY_F  0.1f

// Channel-last fp16 scratch: [k][h][w][c], 16 MB
__device__ __half g_imgT[L_FRAMES * HW * C_CH];

// ---------------------------------------------------------------------------
// Prep: transpose img [k][c][h][w] fp32 -> [k][h][w][c] fp16.
// ---------------------------------------------------------------------------
__global__ void prep_kernel(const float* __restrict__ img) {
    const int kh = blockIdx.x;          // k*H + h
    const int w  = threadIdx.x;         // 0..255
    const int k  = kh >> 7;
    const int h  = kh & (H_DIM - 1);

    __half2 v[8];
#pragma unroll
    for (int c = 0; c < 8; c++) {
        float a = img[((k * C_CH + 2 * c + 0) * H_DIM + h) * W_DIM + w];
        float b = img[((k * C_CH + 2 * c + 1) * H_DIM + h) * W_DIM + w];
        v[c] = __floats2half2_rn(a, b);
    }
    uint4* dst = reinterpret_cast<uint4*>(&g_imgT[((size_t)kh * W_DIM + w) * C_CH]);
    dst[0] = *reinterpret_cast<const uint4*>(&v[0]);
    dst[1] = *reinterpret_cast<const uint4*>(&v[4]);
}

// ---------------------------------------------------------------------------
// Warped accumulation. blockIdx.y = t, blockIdx.x covers 64 pixels.
// 4 lanes per pixel: ch = sub&1 (16B channel half), xh = sub>>1 (x tap).
// Flow staged in SMEM straight from cum_flow. k processed in pairs: tap
// results of 2 k's accumulate in half2 before one fp32 convert+add.
// ---------------------------------------------------------------------------
__global__ void __launch_bounds__(256) sample_kernel(
    const float* __restrict__ cum_flow,   // [k][2][h][w]
    const float* __restrict__ mask,       // [t][k]
    const float* __restrict__ dist,       // [t][k]
    float* __restrict__ out)              // [t][c][h][w]
{
    const int t = blockIdx.y;
    const int p0 = blockIdx.x * 64;

    __shared__ float  ws[L_FRAMES];
    __shared__ float2 sflow[L_FRAMES * 64];   // [k][px], 8 KB

    if (threadIdx.x < L_FRAMES) {
        int i = t * L_FRAMES + threadIdx.x;
        ws[threadIdx.x] = mask[i] * expf(-DECAY_F * dist[i]);
    }
    // cooperative flow stage: 1024 (k,px) pairs, 256 threads -> 4 each
#pragma unroll
    for (int i = 0; i < 4; i++) {
        const int idx = threadIdx.x + i * 256;      // k*64 + px
        const int kk  = idx >> 6;
        const int px  = idx & 63;
        const float fx = cum_flow[(kk * 2 + 0) * HW + p0 + px];
        const float fy = cum_flow[(kk * 2 + 1) * HW + p0 + px];
        sflow[idx] = make_float2(fx, fy);
    }
    __syncthreads();

    const int tid = threadIdx.x;
    const int sub = tid & 3;
    const int ch  = sub & 1;        // channel half: channels [ch*8, ch*8+8)
    const int xh  = sub >> 1;       // x tap: 0 -> x0, 1 -> x0+1
    const int px  = tid >> 2;       // pixel-in-block 0..63
    const int p   = p0 + px;
    const int h   = p >> 8;
    const int w   = p & (W_DIM - 1);

    const float2 ft = sflow[t * 64 + px];

    // Hoisted affine coords: ix = Ax - 128*fkx ; iy = Ay - 64*fky
    const float base_x = (float)w * (2.0f / W_DIM) - 1.0f + (1.0f / W_DIM);
    const float base_y = (float)h * (2.0f / H_DIM) - 1.0f + (1.0f / H_DIM);
    const float Ax = (base_x + ft.x + 1.0f) * (W_DIM * 0.5f) - 0.5f;
    const float Ay = (base_y + ft.y + 1.0f) * (H_DIM * 0.5f) - 0.5f;

    // xw = xh ? wx : 1-wx  ->  xw = fma(sx, wx, cx)
    const float sx = xh ? 1.0f : -1.0f;
    const float cx = xh ? 0.0f : 1.0f;

    float acc[8];
#pragma unroll
    for (int j = 0; j < 8; j++) acc[j] = 0.0f;

    const char* __restrict__ gbase =
        reinterpret_cast<const char*>(g_imgT) + ch * 16;

    // Computes offsets + fp16 weights for frame kk into named outputs.
#define COORDS(kk, OFF0, OFF1, W0H, W1H)                                       \
    unsigned OFF0, OFF1; __half2 W0H, W1H;                                     \
    {                                                                          \
        const float wk  = ws[(kk)];                                            \
        const float2 fk = sflow[(kk) * 64 + px];                               \
        const float ix = fmaf(-(W_DIM * 0.5f), fk.x, Ax);                      \
        const float iy = fmaf(-(H_DIM * 0.5f), fk.y, Ay);                      \
        const int x0 = __float2int_rd(ix);                                     \
        const int y0 = __float2int_rd(iy);                                     \
        const float wx = ix - (float)x0;                                       \
        const float wy = iy - (float)y0;                                       \
        const int x   = (x0 + xh) & (W_DIM - 1);                               \
        const int y0c = min(max(y0, 0), H_DIM - 1);                            \
        const int y1c = min(max(y0 + 1, 0), H_DIM - 1);                        \
        const float xw = fmaf(sx, wx, cx);                                     \
        const float tw = wk * xw;                                              \
        const float w1 = tw * wy;                                              \
        const float w0 = tw - w1;                                              \
        W0H = __float2half2_rn(w0);                                            \
        W1H = __float2half2_rn(w1);                                            \
        const unsigned kb = (unsigned)((kk) * HW) << 5;                        \
        const unsigned ox = (unsigned)x << 5;                                  \
        OFF0 = kb + ((unsigned)y0c << 13) + ox;                                \
        OFF1 = kb + ((unsigned)y1c << 13) + ox;                                \
    }

    // One k: half2 tap combine -> fp32 accumulate
#define BODY1(kk)                                                              \
    {                                                                          \
        COORDS(kk, o0, o1, w0h, w1h);                                          \
        const uint4 u0 = *reinterpret_cast<const uint4*>(gbase + o0);          \
        const uint4 u1 = *reinterpret_cast<const uint4*>(gbase + o1);          \
        const __half2* h0 = reinterpret_cast<const __half2*>(&u0);             \
        const __half2* h1 = reinterpret_cast<const __half2*>(&u1);             \
        _Pragma("unroll")                                                      \
        for (int j = 0; j < 4; j++) {                                          \
            __half2 s = __hmul2(h0[j], w0h);                                   \
            s = __hfma2(h1[j], w1h, s);                                        \
            const float2 f = __half22float2(s);                                \
            acc[2 * j + 0] += f.x;                                             \
            acc[2 * j + 1] += f.y;                                             \
        }                                                                      \
    }

    // Two k's: both LDG pairs in flight, pair-combine in half2, one convert.
#define BODY2(kk)                                                              \
    {                                                                          \
        COORDS((kk) + 0, a0, a1, aw0, aw1);                                    \
        COORDS((kk) + 1, b0, b1, bw0, bw1);                                    \
        const uint4 ua0 = *reinterpret_cast<const uint4*>(gbase + a0);         \
        const uint4 ua1 = *reinterpret_cast<const uint4*>(gbase + a1);         \
        const uint4 ub0 = *reinterpret_cast<const uint4*>(gbase + b0);         \
        const uint4 ub1 = *reinterpret_cast<const uint4*>(gbase + b1);         \
        const __half2* ha0 = reinterpret_cast<const __half2*>(&ua0);           \
        const __half2* ha1 = reinterpret_cast<const __half2*>(&ua1);           \
        const __half2* hb0 = reinterpret_cast<const __half2*>(&ub0);           \
        const __half2* hb1 = reinterpret_cast<const __half2*>(&ub1);           \
        _Pragma("unroll")                                                      \
        for (int j = 0; j < 4; j++) {                                          \
            __half2 s = __hmul2(ha0[j], aw0);                                  \
            s = __hfma2(ha1[j], aw1, s);                                       \
            s = __hfma2(hb0[j], bw0, s);                                       \
            s = __hfma2(hb1[j], bw1, s);                                       \
            const float2 f = __half22float2(s);                                \
            acc[2 * j + 0] += f.x;                                             \
            acc[2 * j + 1] += f.y;                                             \
        }                                                                      \
    }

    int k = 0;
#pragma unroll 2
    for (; k + 1 <= t; k += 2) {
        BODY2(k);
    }
    if (k <= t) BODY1(k);
#undef BODY2
#undef BODY1
#undef COORDS

    // merge x-halves: partner lane differs in bit 1 of tid
#pragma unroll
    for (int j = 0; j < 8; j++)
        acc[j] += __shfl_xor_sync(0xffffffffu, acc[j], 2);

    // each lane writes 4 channels: [ch*8 + xh*4, +4)
    const int cbase = (t * C_CH + ch * 8 + xh * 4) * HW + p;
#pragma unroll
    for (int j = 0; j < 4; j++)
        out[cbase + j * HW] = acc[xh * 4 + j];
}

extern "C" void kernel_launch(void* const* d_in, const int* in_sizes, int n_in,
                              void* d_out, int out_size) {
    const float* img      = (const float*)d_in[0];  // (1,16,16,128,256)
    const float* cum_flow = (const float*)d_in[1];  // (1,16,2,128,256)
    const float* mask     = (const float*)d_in[2];  // (16,16)
    const float* dist     = (const float*)d_in[3];  // (16,16)
    float* out            = (float*)d_out;          // (1,16,16,128,256)

    prep_kernel<<<L_FRAMES * H_DIM, W_DIM>>>(img);

    dim3 grid(HW / 64, L_FRAMES);   // 512 x 16 blocks
    sample_kernel<<<grid, 256>>>(cum_flow, mask, dist, out);
}